// round 12
// baseline (speedup 1.0000x reference)
#include <cuda_runtime.h>

// DTCWT 1D forward, 3 levels, fused. T3=512 / 512-thread blocks.
// Level 1: own-data float4 LDG.cs + warp shuffles -> 20-float register window.
// Levels 2-3: conflict-free pair-per-thread polyphase smem, shared windows.
// Streaming hints: __ldcs for x (read-once), __stcs for outputs (write-once).
// x: [64,1,2^20] fp32. Outputs: lo3 [64,131072], yh0 [64,524288],
// yh1 [64,2,262144], yh2 [64,2,131072], flattened in that order.

#define T3   512
#define NT   512
#define L_IN (1 << 20)
#define L1N  (L_IN / 2)
#define L2N  (L_IN / 4)
#define L3N  (L_IN / 8)

#define L1H  1042   // per-phase lo1 tile (2084 outputs), l1base = 4*o3-18
#define L2H  518    // per-phase lo2 tile (1036 outputs), l2base = 2*o3-6

// q-shift filters split into even/odd taps (exact fp32 of reference arrays)
#define DEF_QLO \
    const float f0ae[7] = { 0.00325314f,  0.03466035f, -0.11720389f,  0.75614564f, \
                            0.01186609f,  0.02382538f, -0.00543948f}; \
    const float f0ao[7] = {-0.00388321f, -0.03887280f,  0.27529538f,  0.56881042f, \
                           -0.10671180f,  0.01702522f, -0.00455690f}
#define DEF_QHI \
    const float f1ae[7] = {-0.00455690f,  0.01702522f, -0.10671180f,  0.56881042f, \
                            0.27529538f, -0.03887280f, -0.00388321f}; \
    const float f1ao[7] = { 0.00543948f, -0.02382538f, -0.01186609f, -0.75614564f, \
                            0.11720389f, -0.03466035f, -0.00325314f}; \
    const float f1be[7] = {-0.00325314f, -0.03466035f,  0.11720389f, -0.75614564f, \
                           -0.01186609f, -0.02382538f,  0.00543948f}; \
    const float f1bo[7] = {-0.00388321f, -0.03887280f,  0.27529538f,  0.56881042f, \
                           -0.10671180f,  0.01702522f, -0.00455690f}

__device__ __forceinline__ float4 shfl_up4(float4 v) {
    float4 r;
    r.x = __shfl_up_sync(0xFFFFFFFFu, v.x, 1);
    r.y = __shfl_up_sync(0xFFFFFFFFu, v.y, 1);
    r.z = __shfl_up_sync(0xFFFFFFFFu, v.z, 1);
    r.w = __shfl_up_sync(0xFFFFFFFFu, v.w, 1);
    return r;
}
__device__ __forceinline__ float4 shfl_dn4(float4 v) {
    float4 r;
    r.x = __shfl_down_sync(0xFFFFFFFFu, v.x, 1);
    r.y = __shfl_down_sync(0xFFFFFFFFu, v.y, 1);
    r.z = __shfl_down_sync(0xFFFFFFFFu, v.z, 1);
    r.w = __shfl_down_sync(0xFFFFFFFFu, v.w, 1);
    return r;
}

__global__ __launch_bounds__(NT, 3)
void dtcwt3_big_kernel(
    const float* __restrict__ x,
    float* __restrict__ out_lo3, float* __restrict__ out_hi1,
    float* __restrict__ out_yh1, float* __restrict__ out_yh2)
{
    __shared__ __align__(8) float s1e[L1H], s1o[L1H];
    __shared__ __align__(8) float s2e[L2H], s2o[L2H];

    const int tid  = threadIdx.x;
    const int lane = tid & 31;
    const int row  = blockIdx.y;
    const int o3   = blockIdx.x * T3;
    const float* __restrict__ xr = x + (size_t)row * L_IN;
    const bool boundary = (blockIdx.x == 0) || (blockIdx.x == gridDim.x - 1);

    // ================= LEVEL 1 (shuffle-assembled register windows) ========
    {
        // window w[k] = x[8*o3 + 8*tid - 4 + k], k = 0..19
        float w[20];
        if (!boundary) {
            const int wb = 8 * o3 + 8 * tid;        // own 8 floats
            float4 v0 = __ldcs(reinterpret_cast<const float4*>(xr + wb));
            float4 v1 = __ldcs(reinterpret_cast<const float4*>(xr + wb + 4));
            float4 up1 = shfl_up4(v1);              // x[wb-4..wb-1]
            float4 dn0 = shfl_dn4(v0);              // x[wb+8..wb+11]
            float4 dn1 = shfl_dn4(v1);              // x[wb+12..wb+15]
            if (lane == 0)
                up1 = __ldcs(reinterpret_cast<const float4*>(xr + wb - 4));
            if (lane == 31) {
                dn0 = __ldcs(reinterpret_cast<const float4*>(xr + wb + 8));
                dn1 = __ldcs(reinterpret_cast<const float4*>(xr + wb + 12));
            }
            w[0]=up1.x; w[1]=up1.y; w[2]=up1.z; w[3]=up1.w;
            w[4]=v0.x;  w[5]=v0.y;  w[6]=v0.z;  w[7]=v0.w;
            w[8]=v1.x;  w[9]=v1.y;  w[10]=v1.z; w[11]=v1.w;
            w[12]=dn0.x; w[13]=dn0.y; w[14]=dn0.z; w[15]=dn0.w;
            w[16]=dn1.x; w[17]=dn1.y; w[18]=dn1.z; w[19]=dn1.w;
        } else {
            const int gbase = 8 * o3 + 8 * tid - 4;
            #pragma unroll
            for (int k = 0; k < 20; k++) {
                int g = gbase + k;
                w[k] = ((unsigned)g < (unsigned)L_IN) ? xr[g] : 0.f;
            }
        }

        // hi quad tid: outputs i = 4*o3 + 4*tid + r, window w[2r+1 .. 2r+7]
        {
            const float c0 = -0.0107143f, c1 = 0.0535714f,
                        c2 =  0.2607143f, c3 = -0.6071429f;
            float4 y;
            float* yp = &y.x;
            #pragma unroll
            for (int r = 0; r < 4; r++) {
                int b = 2 * r + 1;
                yp[r] = fmaf(c0, w[b] + w[b+6],
                        fmaf(c1, w[b+1] + w[b+5],
                        fmaf(c2, w[b+2] + w[b+4], c3 * w[b+3])));
            }
            __stcs(reinterpret_cast<float4*>(
                out_hi1 + (size_t)row * L1N + 4 * o3 + 4 * tid), y);
        }

        // lo quad u = tid+5: local idx 4u+r, j = 4*o3+4*tid+2+r, window w[2r+6..2r+10]
        {
            const int u = tid + 5;
            const int j0 = 4 * o3 + 4 * tid + 2;
            float yl[4];
            #pragma unroll
            for (int r = 0; r < 4; r++) {
                int b = 2 * r + 6;
                float v = fmaf(-0.05f, w[b] + w[b+4],
                          fmaf( 0.6f,  w[b+2],
                                0.25f * (w[b+1] + w[b+3])));
                if ((unsigned)(j0 + r) >= (unsigned)L1N) v = 0.f;
                yl[r] = v;
            }
            *reinterpret_cast<float2*>(&s1e[2*u]) = make_float2(yl[0], yl[2]);
            *reinterpret_cast<float2*>(&s1o[2*u]) = make_float2(yl[1], yl[3]);
        }
    }

    // leftover lo quads u in {0..4} u {517..520} on tids 0..8
    if (tid < 9) {
        const int u = (tid < 5) ? tid : tid + 512;
        const int gb2 = 8 * o3 + 8 * u - 40;   // w2[k] = x[gb2+k], k=0..15
        float w2[16];
        if (!boundary) {
            #pragma unroll
            for (int q = 0; q < 4; q++) {
                float4 v = __ldcs(reinterpret_cast<const float4*>(xr + gb2 + 4 * q));
                w2[4*q] = v.x; w2[4*q+1] = v.y; w2[4*q+2] = v.z; w2[4*q+3] = v.w;
            }
        } else {
            #pragma unroll
            for (int k = 0; k < 16; k++) {
                int g = gb2 + k;
                w2[k] = ((unsigned)g < (unsigned)L_IN) ? xr[g] : 0.f;
            }
        }
        const int j0 = 4 * o3 - 18 + 4 * u;
        float yl[4];
        #pragma unroll
        for (int r = 0; r < 4; r++) {
            int b = 2 * r + 2;
            float v = fmaf(-0.05f, w2[b] + w2[b+4],
                      fmaf( 0.6f,  w2[b+2],
                            0.25f * (w2[b+1] + w2[b+3])));
            if ((unsigned)(j0 + r) >= (unsigned)L1N) v = 0.f;
            yl[r] = v;
        }
        *reinterpret_cast<float2*>(&s1e[2*u]) = make_float2(yl[0], yl[2]);
        *reinterpret_cast<float2*>(&s1o[2*u]) = make_float2(yl[1], yl[3]);
    }
    __syncthreads();

    // ================= LEVEL 2 (merged lo+hi, shared window) ================
    {
        DEF_QLO; DEF_QHI;
        const float2* p1e = reinterpret_cast<const float2*>(s1e);
        const float2* p1o = reinterpret_cast<const float2*>(s1o);
        float* dsta = out_yh1 + (size_t)row * (2 * (size_t)L2N) + 2 * o3;

        #pragma unroll
        for (int it = 0; it < 2; it++) {
            int t = (it == 0) ? tid : tid + NT;
            if (it == 0 || tid < L2H - NT) {
                float ve[8], vo[8];
                #pragma unroll
                for (int k = 0; k < 4; k++) {
                    float2 pe = p1e[t + k], po = p1o[t + k];
                    ve[2*k] = pe.x; ve[2*k+1] = pe.y;
                    vo[2*k] = po.x; vo[2*k+1] = po.y;
                }
                // lowpass pair (local idx 2t, 2t+1)
                float y0 = 0.f, y1 = 0.f;
                #pragma unroll
                for (int k = 0; k < 7; k++) {
                    y0 = fmaf(ve[k],   f0ae[k], y0); y0 = fmaf(vo[k],   f0ao[k], y0);
                    y1 = fmaf(ve[k+1], f0ae[k], y1); y1 = fmaf(vo[k+1], f0ao[k], y1);
                }
                int g0 = (2 * o3 - 6) + 2 * t;
                if ((unsigned)g0       >= (unsigned)L2N) y0 = 0.f;
                if ((unsigned)(g0 + 1) >= (unsigned)L2N) y1 = 0.f;
                s2e[t] = y0;
                s2o[t] = y1;
                // highpass pair m = t-3 (trees a,b) from the SAME window
                int m = t - 3;
                if ((unsigned)m < (unsigned)(2 * T3 / 2)) {
                    float a0 = 0.f, a1 = 0.f, b0 = 0.f, b1 = 0.f;
                    #pragma unroll
                    for (int k = 0; k < 7; k++) {
                        float e0 = ve[k], e1 = ve[k+1], q0 = vo[k], q1 = vo[k+1];
                        a0 = fmaf(e0, f1ae[k], a0); a0 = fmaf(q0, f1ao[k], a0);
                        a1 = fmaf(e1, f1ae[k], a1); a1 = fmaf(q1, f1ao[k], a1);
                        b0 = fmaf(e0, f1be[k], b0); b0 = fmaf(q0, f1bo[k], b0);
                        b1 = fmaf(e1, f1be[k], b1); b1 = fmaf(q1, f1bo[k], b1);
                    }
                    __stcs(reinterpret_cast<float2*>(dsta) + m,       make_float2(a0, a1));
                    __stcs(reinterpret_cast<float2*>(dsta + L2N) + m, make_float2(b0, b1));
                }
            }
        }
    }
    __syncthreads();

    // ================= LEVEL 3 (lo, a, b share one window) ==================
    if (tid < T3 / 2) {
        DEF_QLO; DEF_QHI;
        const float2* p2e = reinterpret_cast<const float2*>(s2e);
        const float2* p2o = reinterpret_cast<const float2*>(s2o);
        int t = tid;
        float ve[8], vo[8];
        #pragma unroll
        for (int k = 0; k < 4; k++) {
            float2 pe = p2e[t + k], po = p2o[t + k];
            ve[2*k] = pe.x; ve[2*k+1] = pe.y;
            vo[2*k] = po.x; vo[2*k+1] = po.y;
        }
        float l0 = 0.f, l1 = 0.f, a0 = 0.f, a1 = 0.f, b0 = 0.f, b1 = 0.f;
        #pragma unroll
        for (int k = 0; k < 7; k++) {
            float e0 = ve[k], e1 = ve[k+1], q0 = vo[k], q1 = vo[k+1];
            l0 = fmaf(e0, f0ae[k], l0); l0 = fmaf(q0, f0ao[k], l0);
            l1 = fmaf(e1, f0ae[k], l1); l1 = fmaf(q1, f0ao[k], l1);
            a0 = fmaf(e0, f1ae[k], a0); a0 = fmaf(q0, f1ao[k], a0);
            a1 = fmaf(e1, f1ae[k], a1); a1 = fmaf(q1, f1ao[k], a1);
            b0 = fmaf(e0, f1be[k], b0); b0 = fmaf(q0, f1bo[k], b0);
            b1 = fmaf(e1, f1be[k], b1); b1 = fmaf(q1, f1bo[k], b1);
        }
        float* dlo  = out_lo3 + (size_t)row * L3N + o3;
        float* dsta = out_yh2 + (size_t)row * (2 * (size_t)L3N) + o3;
        __stcs(reinterpret_cast<float2*>(dlo)        + t, make_float2(l0, l1));
        __stcs(reinterpret_cast<float2*>(dsta)       + t, make_float2(a0, a1));
        __stcs(reinterpret_cast<float2*>(dsta + L3N) + t, make_float2(b0, b1));
    }
}

extern "C" void kernel_launch(void* const* d_in, const int* in_sizes, int n_in,
                              void* d_out, int out_size)
{
    const float* x = (const float*)d_in[0];   // filters folded as immediates

    float* out = (float*)d_out;
    float* out_lo3 = out;                                   // 64 * 131072
    float* out_hi1 = out_lo3 + (size_t)64 * L3N;            // 64 * 524288
    float* out_yh1 = out_hi1 + (size_t)64 * L1N;            // 64 * 2 * 262144
    float* out_yh2 = out_yh1 + (size_t)64 * 2 * L2N;        // 64 * 2 * 131072

    dim3 grid(L3N / T3, 64);
    dtcwt3_big_kernel<<<grid, NT>>>(x, out_lo3, out_hi1, out_yh1, out_yh2);
}

// round 13
// speedup vs baseline: 1.1268x; 1.1268x over previous
#include <cuda_runtime.h>

// DTCWT 1D forward, 3 levels, fused. R11 skeleton (T3=256, shuffle level-1,
// polyphase pair-per-thread levels 2-3) + algebraic filter sharing:
//   b-tree = SO - SE (shares all FMAs with lowpass SE+SO)
//   a-tree = reversed-window correlation with the same f0 immediates.
// Output stores use __stcs (write-once); x loads default (halo L2 reuse).
// x: [64,1,2^20] fp32. Outputs: lo3 [64,131072], yh0 [64,524288],
// yh1 [64,2,262144], yh2 [64,2,131072], flattened in that order.

#define T3   256
#define L_IN (1 << 20)
#define L1N  (L_IN / 2)
#define L2N  (L_IN / 4)
#define L3N  (L_IN / 8)

#define L1H  530    // per-phase lo1 tile (1060 outputs), l1base = 4*o3-18
#define L2H  262    // per-phase lo2 tile (524 outputs),  l2base = 2*o3-6

// q-shift lowpass even/odd taps (exact fp32 of reference arrays).
// Highpass trees derive exactly: f1be[k]=-f0ae[k], f1bo[k]=f0ao[k],
// f1ae[k]=f0ao[6-k], f1ao[k]=-f0ae[6-k].
#define DEF_QLO \
    const float f0ae[7] = { 0.00325314f,  0.03466035f, -0.11720389f,  0.75614564f, \
                            0.01186609f,  0.02382538f, -0.00543948f}; \
    const float f0ao[7] = {-0.00388321f, -0.03887280f,  0.27529538f,  0.56881042f, \
                           -0.10671180f,  0.01702522f, -0.00455690f}

__device__ __forceinline__ float4 shfl_up4(float4 v) {
    float4 r;
    r.x = __shfl_up_sync(0xFFFFFFFFu, v.x, 1);
    r.y = __shfl_up_sync(0xFFFFFFFFu, v.y, 1);
    r.z = __shfl_up_sync(0xFFFFFFFFu, v.z, 1);
    r.w = __shfl_up_sync(0xFFFFFFFFu, v.w, 1);
    return r;
}
__device__ __forceinline__ float4 shfl_dn4(float4 v) {
    float4 r;
    r.x = __shfl_down_sync(0xFFFFFFFFu, v.x, 1);
    r.y = __shfl_down_sync(0xFFFFFFFFu, v.y, 1);
    r.z = __shfl_down_sync(0xFFFFFFFFu, v.z, 1);
    r.w = __shfl_down_sync(0xFFFFFFFFu, v.w, 1);
    return r;
}

__global__ __launch_bounds__(256, 6)
void dtcwt3_alg_kernel(
    const float* __restrict__ x,
    float* __restrict__ out_lo3, float* __restrict__ out_hi1,
    float* __restrict__ out_yh1, float* __restrict__ out_yh2)
{
    __shared__ __align__(8) float s1e[L1H], s1o[L1H];
    __shared__ __align__(8) float s2e[L2H], s2o[L2H];

    const int tid  = threadIdx.x;
    const int lane = tid & 31;
    const int row  = blockIdx.y;
    const int o3   = blockIdx.x * T3;
    const float* __restrict__ xr = x + (size_t)row * L_IN;
    const bool boundary = (blockIdx.x == 0) || (blockIdx.x == gridDim.x - 1);

    // ================= LEVEL 1 (shuffle-assembled register windows) ========
    {
        // window w[k] = x[8*o3 + 8*tid - 4 + k], k = 0..19
        float w[20];
        if (!boundary) {
            const int wb = 8 * o3 + 8 * tid;        // own 8 floats
            float4 v0 = *reinterpret_cast<const float4*>(xr + wb);
            float4 v1 = *reinterpret_cast<const float4*>(xr + wb + 4);
            float4 up1 = shfl_up4(v1);              // x[wb-4..wb-1]
            float4 dn0 = shfl_dn4(v0);              // x[wb+8..wb+11]
            float4 dn1 = shfl_dn4(v1);              // x[wb+12..wb+15]
            if (lane == 0)
                up1 = *reinterpret_cast<const float4*>(xr + wb - 4);
            if (lane == 31) {
                dn0 = *reinterpret_cast<const float4*>(xr + wb + 8);
                dn1 = *reinterpret_cast<const float4*>(xr + wb + 12);
            }
            w[0]=up1.x; w[1]=up1.y; w[2]=up1.z; w[3]=up1.w;
            w[4]=v0.x;  w[5]=v0.y;  w[6]=v0.z;  w[7]=v0.w;
            w[8]=v1.x;  w[9]=v1.y;  w[10]=v1.z; w[11]=v1.w;
            w[12]=dn0.x; w[13]=dn0.y; w[14]=dn0.z; w[15]=dn0.w;
            w[16]=dn1.x; w[17]=dn1.y; w[18]=dn1.z; w[19]=dn1.w;
        } else {
            const int gbase = 8 * o3 + 8 * tid - 4;
            #pragma unroll
            for (int k = 0; k < 20; k++) {
                int g = gbase + k;
                w[k] = ((unsigned)g < (unsigned)L_IN) ? xr[g] : 0.f;
            }
        }

        // hi quad tid: outputs i = 4*o3 + 4*tid + r, window w[2r+1 .. 2r+7]
        {
            const float c0 = -0.0107143f, c1 = 0.0535714f,
                        c2 =  0.2607143f, c3 = -0.6071429f;
            float4 y;
            float* yp = &y.x;
            #pragma unroll
            for (int r = 0; r < 4; r++) {
                int b = 2 * r + 1;
                yp[r] = fmaf(c0, w[b] + w[b+6],
                        fmaf(c1, w[b+1] + w[b+5],
                        fmaf(c2, w[b+2] + w[b+4], c3 * w[b+3])));
            }
            __stcs(reinterpret_cast<float4*>(
                out_hi1 + (size_t)row * L1N + 4 * o3 + 4 * tid), y);
        }

        // lo quad u = tid+5: local idx 4u+r, j = 4*o3+4*tid+2+r, window w[2r+6..2r+10]
        {
            const int u = tid + 5;
            const int j0 = 4 * o3 + 4 * tid + 2;
            float yl[4];
            #pragma unroll
            for (int r = 0; r < 4; r++) {
                int b = 2 * r + 6;
                float v = fmaf(-0.05f, w[b] + w[b+4],
                          fmaf( 0.6f,  w[b+2],
                                0.25f * (w[b+1] + w[b+3])));
                if ((unsigned)(j0 + r) >= (unsigned)L1N) v = 0.f;
                yl[r] = v;
            }
            *reinterpret_cast<float2*>(&s1e[2*u]) = make_float2(yl[0], yl[2]);
            *reinterpret_cast<float2*>(&s1o[2*u]) = make_float2(yl[1], yl[3]);
        }
    }

    // leftover lo quads u in {0..4} u {261..264} on tids 0..8
    if (tid < 9) {
        const int u = (tid < 5) ? tid : tid + 256;
        const int gb2 = 8 * o3 + 8 * u - 40;   // w2[k] = x[gb2+k], k=0..15
        float w2[16];
        if (!boundary) {
            #pragma unroll
            for (int q = 0; q < 4; q++) {
                float4 v = *reinterpret_cast<const float4*>(xr + gb2 + 4 * q);
                w2[4*q] = v.x; w2[4*q+1] = v.y; w2[4*q+2] = v.z; w2[4*q+3] = v.w;
            }
        } else {
            #pragma unroll
            for (int k = 0; k < 16; k++) {
                int g = gb2 + k;
                w2[k] = ((unsigned)g < (unsigned)L_IN) ? xr[g] : 0.f;
            }
        }
        const int j0 = 4 * o3 - 18 + 4 * u;
        float yl[4];
        #pragma unroll
        for (int r = 0; r < 4; r++) {
            int b = 2 * r + 2;
            float v = fmaf(-0.05f, w2[b] + w2[b+4],
                      fmaf( 0.6f,  w2[b+2],
                            0.25f * (w2[b+1] + w2[b+3])));
            if ((unsigned)(j0 + r) >= (unsigned)L1N) v = 0.f;
            yl[r] = v;
        }
        *reinterpret_cast<float2*>(&s1e[2*u]) = make_float2(yl[0], yl[2]);
        *reinterpret_cast<float2*>(&s1o[2*u]) = make_float2(yl[1], yl[3]);
    }
    __syncthreads();

    // ======= LEVEL 2 (merged: SE/SO shared by lo and tree-b; tree-a rev) ====
    {
        DEF_QLO;
        const float2* p1e = reinterpret_cast<const float2*>(s1e);
        const float2* p1o = reinterpret_cast<const float2*>(s1o);
        float* dsta = out_yh1 + (size_t)row * (2 * (size_t)L2N) + 2 * o3;

        #pragma unroll
        for (int it = 0; it < 2; it++) {
            int t = (it == 0) ? tid : tid + 256;
            if (it == 0 || tid < L2H - 256) {
                float ve[8], vo[8];
                #pragma unroll
                for (int k = 0; k < 4; k++) {
                    float2 pe = p1e[t + k], po = p1o[t + k];
                    ve[2*k] = pe.x; ve[2*k+1] = pe.y;
                    vo[2*k] = po.x; vo[2*k+1] = po.y;
                }
                float SE0 = 0.f, SE1 = 0.f, SO0 = 0.f, SO1 = 0.f;
                float A0 = 0.f, A1 = 0.f;
                #pragma unroll
                for (int k = 0; k < 7; k++) {
                    SE0 = fmaf(ve[k],   f0ae[k], SE0);
                    SE1 = fmaf(ve[k+1], f0ae[k], SE1);
                    SO0 = fmaf(vo[k],   f0ao[k], SO0);
                    SO1 = fmaf(vo[k+1], f0ao[k], SO1);
                    A0  = fmaf(ve[k],    f0ao[6-k], A0);
                    A0  = fmaf(vo[k],   -f0ae[6-k], A0);
                    A1  = fmaf(ve[k+1],  f0ao[6-k], A1);
                    A1  = fmaf(vo[k+1], -f0ae[6-k], A1);
                }
                // lowpass pair (local idx 2t, 2t+1)
                float y0 = SE0 + SO0, y1 = SE1 + SO1;
                int g0 = (2 * o3 - 6) + 2 * t;
                if ((unsigned)g0       >= (unsigned)L2N) y0 = 0.f;
                if ((unsigned)(g0 + 1) >= (unsigned)L2N) y1 = 0.f;
                s2e[t] = y0;
                s2o[t] = y1;
                // highpass pair m = t-3 (trees a,b) from the SAME window
                int m = t - 3;
                if ((unsigned)m < 256u) {
                    __stcs(reinterpret_cast<float2*>(dsta) + m,
                           make_float2(A0, A1));
                    __stcs(reinterpret_cast<float2*>(dsta + L2N) + m,
                           make_float2(SO0 - SE0, SO1 - SE1));
                }
            }
        }
    }
    __syncthreads();

    // ======= LEVEL 3 (SE/SO shared by lo and tree-b; tree-a reversed) =======
    if (tid < T3 / 2) {
        DEF_QLO;
        const float2* p2e = reinterpret_cast<const float2*>(s2e);
        const float2* p2o = reinterpret_cast<const float2*>(s2o);
        int t = tid;
        float ve[8], vo[8];
        #pragma unroll
        for (int k = 0; k < 4; k++) {
            float2 pe = p2e[t + k], po = p2o[t + k];
            ve[2*k] = pe.x; ve[2*k+1] = pe.y;
            vo[2*k] = po.x; vo[2*k+1] = po.y;
        }
        float SE0 = 0.f, SE1 = 0.f, SO0 = 0.f, SO1 = 0.f;
        float A0 = 0.f, A1 = 0.f;
        #pragma unroll
        for (int k = 0; k < 7; k++) {
            SE0 = fmaf(ve[k],   f0ae[k], SE0);
            SE1 = fmaf(ve[k+1], f0ae[k], SE1);
            SO0 = fmaf(vo[k],   f0ao[k], SO0);
            SO1 = fmaf(vo[k+1], f0ao[k], SO1);
            A0  = fmaf(ve[k],    f0ao[6-k], A0);
            A0  = fmaf(vo[k],   -f0ae[6-k], A0);
            A1  = fmaf(ve[k+1],  f0ao[6-k], A1);
            A1  = fmaf(vo[k+1], -f0ae[6-k], A1);
        }
        float* dlo  = out_lo3 + (size_t)row * L3N + o3;
        float* dsta = out_yh2 + (size_t)row * (2 * (size_t)L3N) + o3;
        __stcs(reinterpret_cast<float2*>(dlo)        + t,
               make_float2(SE0 + SO0, SE1 + SO1));
        __stcs(reinterpret_cast<float2*>(dsta)       + t,
               make_float2(A0, A1));
        __stcs(reinterpret_cast<float2*>(dsta + L3N) + t,
               make_float2(SO0 - SE0, SO1 - SE1));
    }
}

extern "C" void kernel_launch(void* const* d_in, const int* in_sizes, int n_in,
                              void* d_out, int out_size)
{
    const float* x = (const float*)d_in[0];   // filters folded as immediates

    float* out = (float*)d_out;
    float* out_lo3 = out;                                   // 64 * 131072
    float* out_hi1 = out_lo3 + (size_t)64 * L3N;            // 64 * 524288
    float* out_yh1 = out_hi1 + (size_t)64 * L1N;            // 64 * 2 * 262144
    float* out_yh2 = out_yh1 + (size_t)64 * 2 * L2N;        // 64 * 2 * 131072

    dim3 grid(L3N / T3, 64);
    dtcwt3_alg_kernel<<<grid, 256>>>(x, out_lo3, out_hi1, out_yh1, out_yh2);
}

// round 14
// speedup vs baseline: 1.2037x; 1.0682x over previous
#include <cuda_runtime.h>

// DTCWT 1D forward, 3 levels, fused. R13 + 7-blocks/SM residency cap
// (regs forced <=36 so 56 warps/SM fit; latency hiding across barrier phases).
// Level 1: own-data float4 LDG + warp shuffles -> 20-float register window.
// Levels 2-3: conflict-free pair-per-thread polyphase smem; algebraic filter
// sharing (b-tree = SO-SE shares all FMAs with lowpass; a-tree = reversed f0).
// x: [64,1,2^20] fp32. Outputs: lo3 [64,131072], yh0 [64,524288],
// yh1 [64,2,262144], yh2 [64,2,131072], flattened in that order.

#define T3   256
#define L_IN (1 << 20)
#define L1N  (L_IN / 2)
#define L2N  (L_IN / 4)
#define L3N  (L_IN / 8)

#define L1H  530    // per-phase lo1 tile (1060 outputs), l1base = 4*o3-18
#define L2H  262    // per-phase lo2 tile (524 outputs),  l2base = 2*o3-6

// q-shift lowpass even/odd taps (exact fp32 of reference arrays).
// Highpass trees derive exactly: f1be[k]=-f0ae[k], f1bo[k]=f0ao[k],
// f1ae[k]=f0ao[6-k], f1ao[k]=-f0ae[6-k].
#define DEF_QLO \
    const float f0ae[7] = { 0.00325314f,  0.03466035f, -0.11720389f,  0.75614564f, \
                            0.01186609f,  0.02382538f, -0.00543948f}; \
    const float f0ao[7] = {-0.00388321f, -0.03887280f,  0.27529538f,  0.56881042f, \
                           -0.10671180f,  0.01702522f, -0.00455690f}

__device__ __forceinline__ float4 shfl_up4(float4 v) {
    float4 r;
    r.x = __shfl_up_sync(0xFFFFFFFFu, v.x, 1);
    r.y = __shfl_up_sync(0xFFFFFFFFu, v.y, 1);
    r.z = __shfl_up_sync(0xFFFFFFFFu, v.z, 1);
    r.w = __shfl_up_sync(0xFFFFFFFFu, v.w, 1);
    return r;
}
__device__ __forceinline__ float4 shfl_dn4(float4 v) {
    float4 r;
    r.x = __shfl_down_sync(0xFFFFFFFFu, v.x, 1);
    r.y = __shfl_down_sync(0xFFFFFFFFu, v.y, 1);
    r.z = __shfl_down_sync(0xFFFFFFFFu, v.z, 1);
    r.w = __shfl_down_sync(0xFFFFFFFFu, v.w, 1);
    return r;
}

__global__ __launch_bounds__(256, 7)
void dtcwt3_occ_kernel(
    const float* __restrict__ x,
    float* __restrict__ out_lo3, float* __restrict__ out_hi1,
    float* __restrict__ out_yh1, float* __restrict__ out_yh2)
{
    __shared__ __align__(8) float s1e[L1H], s1o[L1H];
    __shared__ __align__(8) float s2e[L2H], s2o[L2H];

    const int tid  = threadIdx.x;
    const int lane = tid & 31;
    const int row  = blockIdx.y;
    const int o3   = blockIdx.x * T3;
    const float* __restrict__ xr = x + (size_t)row * L_IN;
    const bool boundary = (blockIdx.x == 0) || (blockIdx.x == gridDim.x - 1);

    // ================= LEVEL 1 (shuffle-assembled register windows) ========
    {
        // window w[k] = x[8*o3 + 8*tid - 4 + k], k = 0..19
        float w[20];
        if (!boundary) {
            const int wb = 8 * o3 + 8 * tid;        // own 8 floats
            float4 v0 = *reinterpret_cast<const float4*>(xr + wb);
            float4 v1 = *reinterpret_cast<const float4*>(xr + wb + 4);
            float4 up1 = shfl_up4(v1);              // x[wb-4..wb-1]
            float4 dn0 = shfl_dn4(v0);              // x[wb+8..wb+11]
            float4 dn1 = shfl_dn4(v1);              // x[wb+12..wb+15]
            if (lane == 0)
                up1 = *reinterpret_cast<const float4*>(xr + wb - 4);
            if (lane == 31) {
                dn0 = *reinterpret_cast<const float4*>(xr + wb + 8);
                dn1 = *reinterpret_cast<const float4*>(xr + wb + 12);
            }
            w[0]=up1.x; w[1]=up1.y; w[2]=up1.z; w[3]=up1.w;
            w[4]=v0.x;  w[5]=v0.y;  w[6]=v0.z;  w[7]=v0.w;
            w[8]=v1.x;  w[9]=v1.y;  w[10]=v1.z; w[11]=v1.w;
            w[12]=dn0.x; w[13]=dn0.y; w[14]=dn0.z; w[15]=dn0.w;
            w[16]=dn1.x; w[17]=dn1.y; w[18]=dn1.z; w[19]=dn1.w;
        } else {
            const int gbase = 8 * o3 + 8 * tid - 4;
            #pragma unroll
            for (int k = 0; k < 20; k++) {
                int g = gbase + k;
                w[k] = ((unsigned)g < (unsigned)L_IN) ? xr[g] : 0.f;
            }
        }

        // hi quad tid: outputs i = 4*o3 + 4*tid + r, window w[2r+1 .. 2r+7]
        {
            const float c0 = -0.0107143f, c1 = 0.0535714f,
                        c2 =  0.2607143f, c3 = -0.6071429f;
            float4 y;
            float* yp = &y.x;
            #pragma unroll
            for (int r = 0; r < 4; r++) {
                int b = 2 * r + 1;
                yp[r] = fmaf(c0, w[b] + w[b+6],
                        fmaf(c1, w[b+1] + w[b+5],
                        fmaf(c2, w[b+2] + w[b+4], c3 * w[b+3])));
            }
            __stcs(reinterpret_cast<float4*>(
                out_hi1 + (size_t)row * L1N + 4 * o3 + 4 * tid), y);
        }

        // lo quad u = tid+5: local idx 4u+r, j = 4*o3+4*tid+2+r, window w[2r+6..2r+10]
        {
            const int u = tid + 5;
            const int j0 = 4 * o3 + 4 * tid + 2;
            float yl[4];
            #pragma unroll
            for (int r = 0; r < 4; r++) {
                int b = 2 * r + 6;
                float v = fmaf(-0.05f, w[b] + w[b+4],
                          fmaf( 0.6f,  w[b+2],
                                0.25f * (w[b+1] + w[b+3])));
                if ((unsigned)(j0 + r) >= (unsigned)L1N) v = 0.f;
                yl[r] = v;
            }
            *reinterpret_cast<float2*>(&s1e[2*u]) = make_float2(yl[0], yl[2]);
            *reinterpret_cast<float2*>(&s1o[2*u]) = make_float2(yl[1], yl[3]);
        }
    }

    // leftover lo quads u in {0..4} u {261..264} on tids 0..8
    if (tid < 9) {
        const int u = (tid < 5) ? tid : tid + 256;
        const int gb2 = 8 * o3 + 8 * u - 40;   // w2[k] = x[gb2+k], k=0..15
        float w2[16];
        if (!boundary) {
            #pragma unroll
            for (int q = 0; q < 4; q++) {
                float4 v = *reinterpret_cast<const float4*>(xr + gb2 + 4 * q);
                w2[4*q] = v.x; w2[4*q+1] = v.y; w2[4*q+2] = v.z; w2[4*q+3] = v.w;
            }
        } else {
            #pragma unroll
            for (int k = 0; k < 16; k++) {
                int g = gb2 + k;
                w2[k] = ((unsigned)g < (unsigned)L_IN) ? xr[g] : 0.f;
            }
        }
        const int j0 = 4 * o3 - 18 + 4 * u;
        float yl[4];
        #pragma unroll
        for (int r = 0; r < 4; r++) {
            int b = 2 * r + 2;
            float v = fmaf(-0.05f, w2[b] + w2[b+4],
                      fmaf( 0.6f,  w2[b+2],
                            0.25f * (w2[b+1] + w2[b+3])));
            if ((unsigned)(j0 + r) >= (unsigned)L1N) v = 0.f;
            yl[r] = v;
        }
        *reinterpret_cast<float2*>(&s1e[2*u]) = make_float2(yl[0], yl[2]);
        *reinterpret_cast<float2*>(&s1o[2*u]) = make_float2(yl[1], yl[3]);
    }
    __syncthreads();

    // ======= LEVEL 2 (merged: SE/SO shared by lo and tree-b; tree-a rev) ====
    {
        DEF_QLO;
        const float2* p1e = reinterpret_cast<const float2*>(s1e);
        const float2* p1o = reinterpret_cast<const float2*>(s1o);
        float* dsta = out_yh1 + (size_t)row * (2 * (size_t)L2N) + 2 * o3;

        #pragma unroll
        for (int it = 0; it < 2; it++) {
            int t = (it == 0) ? tid : tid + 256;
            if (it == 0 || tid < L2H - 256) {
                float ve[8], vo[8];
                #pragma unroll
                for (int k = 0; k < 4; k++) {
                    float2 pe = p1e[t + k], po = p1o[t + k];
                    ve[2*k] = pe.x; ve[2*k+1] = pe.y;
                    vo[2*k] = po.x; vo[2*k+1] = po.y;
                }
                float SE0 = 0.f, SE1 = 0.f, SO0 = 0.f, SO1 = 0.f;
                float A0 = 0.f, A1 = 0.f;
                #pragma unroll
                for (int k = 0; k < 7; k++) {
                    SE0 = fmaf(ve[k],   f0ae[k], SE0);
                    SE1 = fmaf(ve[k+1], f0ae[k], SE1);
                    SO0 = fmaf(vo[k],   f0ao[k], SO0);
                    SO1 = fmaf(vo[k+1], f0ao[k], SO1);
                    A0  = fmaf(ve[k],    f0ao[6-k], A0);
                    A0  = fmaf(vo[k],   -f0ae[6-k], A0);
                    A1  = fmaf(ve[k+1],  f0ao[6-k], A1);
                    A1  = fmaf(vo[k+1], -f0ae[6-k], A1);
                }
                // lowpass pair (local idx 2t, 2t+1)
                float y0 = SE0 + SO0, y1 = SE1 + SO1;
                int g0 = (2 * o3 - 6) + 2 * t;
                if ((unsigned)g0       >= (unsigned)L2N) y0 = 0.f;
                if ((unsigned)(g0 + 1) >= (unsigned)L2N) y1 = 0.f;
                s2e[t] = y0;
                s2o[t] = y1;
                // highpass pair m = t-3 (trees a,b) from the SAME window
                int m = t - 3;
                if ((unsigned)m < 256u) {
                    __stcs(reinterpret_cast<float2*>(dsta) + m,
                           make_float2(A0, A1));
                    __stcs(reinterpret_cast<float2*>(dsta + L2N) + m,
                           make_float2(SO0 - SE0, SO1 - SE1));
                }
            }
        }
    }
    __syncthreads();

    // ======= LEVEL 3 (SE/SO shared by lo and tree-b; tree-a reversed) =======
    if (tid < T3 / 2) {
        DEF_QLO;
        const float2* p2e = reinterpret_cast<const float2*>(s2e);
        const float2* p2o = reinterpret_cast<const float2*>(s2o);
        int t = tid;
        float ve[8], vo[8];
        #pragma unroll
        for (int k = 0; k < 4; k++) {
            float2 pe = p2e[t + k], po = p2o[t + k];
            ve[2*k] = pe.x; ve[2*k+1] = pe.y;
            vo[2*k] = po.x; vo[2*k+1] = po.y;
        }
        float SE0 = 0.f, SE1 = 0.f, SO0 = 0.f, SO1 = 0.f;
        float A0 = 0.f, A1 = 0.f;
        #pragma unroll
        for (int k = 0; k < 7; k++) {
            SE0 = fmaf(ve[k],   f0ae[k], SE0);
            SE1 = fmaf(ve[k+1], f0ae[k], SE1);
            SO0 = fmaf(vo[k],   f0ao[k], SO0);
            SO1 = fmaf(vo[k+1], f0ao[k], SO1);
            A0  = fmaf(ve[k],    f0ao[6-k], A0);
            A0  = fmaf(vo[k],   -f0ae[6-k], A0);
            A1  = fmaf(ve[k+1],  f0ao[6-k], A1);
            A1  = fmaf(vo[k+1], -f0ae[6-k], A1);
        }
        float* dlo  = out_lo3 + (size_t)row * L3N + o3;
        float* dsta = out_yh2 + (size_t)row * (2 * (size_t)L3N) + o3;
        __stcs(reinterpret_cast<float2*>(dlo)        + t,
               make_float2(SE0 + SO0, SE1 + SO1));
        __stcs(reinterpret_cast<float2*>(dsta)       + t,
               make_float2(A0, A1));
        __stcs(reinterpret_cast<float2*>(dsta + L3N) + t,
               make_float2(SO0 - SE0, SO1 - SE1));
    }
}

extern "C" void kernel_launch(void* const* d_in, const int* in_sizes, int n_in,
                              void* d_out, int out_size)
{
    const float* x = (const float*)d_in[0];   // filters folded as immediates

    float* out = (float*)d_out;
    float* out_lo3 = out;                                   // 64 * 131072
    float* out_hi1 = out_lo3 + (size_t)64 * L3N;            // 64 * 524288
    float* out_yh1 = out_hi1 + (size_t)64 * L1N;            // 64 * 2 * 262144
    float* out_yh2 = out_yh1 + (size_t)64 * 2 * L2N;        // 64 * 2 * 131072

    dim3 grid(L3N / T3, 64);
    dtcwt3_occ_kernel<<<grid, 256>>>(x, out_lo3, out_hi1, out_yh1, out_yh2);
}